// round 6
// baseline (speedup 1.0000x reference)
#include <cuda_runtime.h>
#include <cuda_fp16.h>
#include <math.h>
#include <cstdint>

#define BATCH  4
#define SEQ    1024
#define DMODEL 1024
#define NH     16
#define DK     64

// ---------------- scratch (device globals: allocation-free) ----------------
__device__ float g_Q[BATCH * NH * SEQ * DK];   // tf32-rounded values
__device__ float g_K[BATCH * NH * SEQ * DK];   // tf32-rounded values
__device__ float g_V[BATCH * NH * SEQ * DK];   // tf32-rounded values
__device__ __half g_biash[(size_t)BATCH * NH * SEQ * SEQ];   // 134 MB, mask folded in
__device__ float g_ctx[BATCH * SEQ * DMODEL];

// ---------------- helpers ----------------
__device__ __forceinline__ float to_tf32(float x) {
    uint32_t u;
    asm("cvt.rna.tf32.f32 %0, %1;" : "=r"(u) : "f"(x));
    return __uint_as_float(u);
}
__device__ __forceinline__ void mma_tf32(float c[4], const uint32_t a[4], const uint32_t b[2]) {
    asm volatile("mma.sync.aligned.m16n8k8.row.col.f32.tf32.tf32.f32 "
                 "{%0,%1,%2,%3}, {%4,%5,%6,%7}, {%8,%9}, {%0,%1,%2,%3};"
                 : "+f"(c[0]), "+f"(c[1]), "+f"(c[2]), "+f"(c[3])
                 : "r"(a[0]), "r"(a[1]), "r"(a[2]), "r"(a[3]), "r"(b[0]), "r"(b[1]));
}
__device__ __forceinline__ uint32_t smem_u32(const void* p) {
    uint32_t a;
    asm("{ .reg .u64 t; cvta.to.shared.u64 t, %1; cvt.u32.u64 %0, t; }" : "=r"(a) : "l"(p));
    return a;
}
__device__ __forceinline__ void cp_async16(uint32_t s, const void* g) {
    asm volatile("cp.async.cg.shared.global [%0], [%1], 16;" :: "r"(s), "l"(g) : "memory");
}
__device__ __forceinline__ void cp_commit() {
    asm volatile("cp.async.commit_group;" ::: "memory");
}
__device__ __forceinline__ void cp_wait1() {
    asm volatile("cp.async.wait_group 1;" ::: "memory");
}

// ---------------------------------------------------------------------------
// Tensor GEMM via mma.sync tf32 (same as R5; QKV epilogue now tf32-rounds)
// ---------------------------------------------------------------------------
#define AP 36
#define BP 136
#define GBUF (128 * AP + 32 * BP)
#define GSMEM_BYTES (2 * GBUF * 4)

__global__ __launch_bounds__(256)
void gemm_mma(const float* __restrict__ A,
              const float* __restrict__ W0, const float* __restrict__ W1,
              const float* __restrict__ W2,
              const float* __restrict__ bias0, const float* __restrict__ bias1,
              const float* __restrict__ bias2,
              float* __restrict__ Cout, int mode)
{
    extern __shared__ float smg[];
    const int tid = threadIdx.x, lane = tid & 31;
    const int wid = tid >> 5;
    const int wm = wid & 3, wn = wid >> 2;
    const int r = lane >> 2, c = lane & 3;

    int mat, bn;
    const float* W;
    const float* bias;
    if (mode == 0) {
        mat = blockIdx.x >> 3;
        bn = (blockIdx.x & 7) * 128;
        W = (mat == 0) ? W0 : (mat == 1) ? W1 : W2;
        bias = (mat == 0) ? bias0 : (mat == 1) ? bias1 : bias2;
    } else {
        mat = 3;
        bn = blockIdx.x * 128;
        W = W0;
        bias = bias0;
    }
    const int bm = blockIdx.y * 128;
    const float* Asrc = (mode == 0) ? A : g_ctx;

    const int arow = tid >> 1;
    const int acb  = (tid & 1) * 16;
    const int brow = tid >> 3;
    const int bcb  = (tid & 7) * 16;
    const float* Apg = Asrc + (size_t)(bm + arow) * 1024 + acb;
    const float* Bpg = W + (size_t)brow * 1024 + bn + bcb;

    float acc[2][8][4];
    #pragma unroll
    for (int im = 0; im < 2; im++)
        #pragma unroll
        for (int in_ = 0; in_ < 8; in_++)
            #pragma unroll
            for (int j = 0; j < 4; j++) acc[im][in_][j] = 0.f;

    float4 ar[4], br[4];
    #pragma unroll
    for (int j = 0; j < 4; j++) {
        ar[j] = *(const float4*)(Apg + j * 4);
        br[j] = *(const float4*)(Bpg + (size_t)0 + j * 4);
    }
    {
        float* Ab = smg;
        float* Bb = smg + 128 * AP;
        #pragma unroll
        for (int j = 0; j < 4; j++) {
            float4 t = { to_tf32(ar[j].x), to_tf32(ar[j].y), to_tf32(ar[j].z), to_tf32(ar[j].w) };
            *(float4*)&Ab[arow * AP + acb + j * 4] = t;
            float4 u = { to_tf32(br[j].x), to_tf32(br[j].y), to_tf32(br[j].z), to_tf32(br[j].w) };
            *(float4*)&Bb[brow * BP + bcb + j * 4] = u;
        }
    }
    __syncthreads();

    for (int s = 0; s < 32; s++) {
        if (s + 1 < 32) {
            const int k0 = (s + 1) * 32;
            #pragma unroll
            for (int j = 0; j < 4; j++) {
                ar[j] = *(const float4*)(Apg + k0 + j * 4);
                br[j] = *(const float4*)(Bpg + (size_t)k0 * 1024 + j * 4);
            }
        }
        const float* Ab = smg + (s & 1) * GBUF;
        const float* Bb = Ab + 128 * AP;
        #pragma unroll
        for (int ks = 0; ks < 4; ks++) {
            uint32_t af[2][4];
            #pragma unroll
            for (int im = 0; im < 2; im++) {
                const int m0 = wm * 32 + im * 16;
                af[im][0] = __float_as_uint(Ab[(m0 + r) * AP + ks * 8 + c]);
                af[im][1] = __float_as_uint(Ab[(m0 + r + 8) * AP + ks * 8 + c]);
                af[im][2] = __float_as_uint(Ab[(m0 + r) * AP + ks * 8 + c + 4]);
                af[im][3] = __float_as_uint(Ab[(m0 + r + 8) * AP + ks * 8 + c + 4]);
            }
            #pragma unroll
            for (int in_ = 0; in_ < 8; in_++) {
                const int n0 = wn * 64 + in_ * 8;
                uint32_t bf[2];
                bf[0] = __float_as_uint(Bb[(ks * 8 + c) * BP + n0 + r]);
                bf[1] = __float_as_uint(Bb[(ks * 8 + c + 4) * BP + n0 + r]);
                mma_tf32(acc[0][in_], af[0], bf);
                mma_tf32(acc[1][in_], af[1], bf);
            }
        }
        if (s + 1 < 32) {
            float* Ab2 = smg + ((s + 1) & 1) * GBUF;
            float* Bb2 = Ab2 + 128 * AP;
            #pragma unroll
            for (int j = 0; j < 4; j++) {
                float4 t = { to_tf32(ar[j].x), to_tf32(ar[j].y), to_tf32(ar[j].z), to_tf32(ar[j].w) };
                *(float4*)&Ab2[arow * AP + acb + j * 4] = t;
                float4 u = { to_tf32(br[j].x), to_tf32(br[j].y), to_tf32(br[j].z), to_tf32(br[j].w) };
                *(float4*)&Bb2[brow * BP + bcb + j * 4] = u;
            }
        }
        __syncthreads();
    }

    #pragma unroll
    for (int im = 0; im < 2; im++) {
        #pragma unroll
        for (int in_ = 0; in_ < 8; in_++) {
            const int m = bm + wm * 32 + im * 16 + r;
            const int n = bn + wn * 64 + in_ * 8 + 2 * c;
            float2 bz = *(const float2*)&bias[n];
            float2 v0 = { acc[im][in_][0] + bz.x, acc[im][in_][1] + bz.y };
            float2 v1 = { acc[im][in_][2] + bz.x, acc[im][in_][3] + bz.y };
            if (mode == 0) {
                // round to tf32 at the producer so attention can cp.async raw
                v0.x = to_tf32(v0.x);  v0.y = to_tf32(v0.y);
                v1.x = to_tf32(v1.x);  v1.y = to_tf32(v1.y);
                const int bb = m >> 10, ss = m & 1023;
                const int hh = n >> 6, dd = n & 63;
                float* dst = ((mat == 0) ? g_Q : (mat == 1) ? g_K : g_V)
                           + ((size_t)((bb * NH + hh) * SEQ + ss)) * DK + dd;
                *(float2*)dst = v0;
                *(float2*)(dst + 8 * DK) = v1;
            } else {
                float* dst = Cout + (size_t)m * 1024 + n;
                *(float2*)dst = v0;
                *(float2*)(dst + 8 * 1024) = v1;
            }
        }
    }
}

// ---------------------------------------------------------------------------
// Geometry bias (fp16, mask folded)
// ---------------------------------------------------------------------------
__global__ __launch_bounds__(256)
void geom_bias_kernel(const float* __restrict__ geom, const float* __restrict__ Wg,
                      const float* __restrict__ bg, const int* __restrict__ mask)
{
    __shared__ float wgs[7][16];
    __shared__ float bgs[16];
    int tid = threadIdx.x;
    if (tid < 112) wgs[tid / 16][tid % 16] = Wg[tid];
    if (tid < 16)  bgs[tid] = bg[tid];
    __syncthreads();

    size_t idx = (size_t)blockIdx.x * 256 + tid;
    const float* gp = geom + idx * 7;
    float g[7];
    #pragma unroll
    for (int i = 0; i < 7; i++) g[i] = gp[i];

    int k = (int)(idx & 1023);
    int bq = (int)(idx >> 10);
    int q = bq & 1023;
    int b = bq >> 10;
    const bool live = mask[b * SEQ + k] != 0;
    size_t base = ((size_t)(b * NH) * SEQ + q) * SEQ + k;

    #pragma unroll
    for (int h = 0; h < NH; h++) {
        float v = bgs[h];
        #pragma unroll
        for (int i = 0; i < 7; i++) v += g[i] * wgs[i][h];
        g_biash[base + (size_t)h * SEQ * SEQ] = __float2half(live ? v : -30000.f);
    }
}

// ---------------------------------------------------------------------------
// Flash attention v3: 128 threads / 4 warps, q-tile 64.
// cp.async double-buffered K/V (raw row-major, padded), Q via cp.async once.
// Conflict-free pads: Q/K/P stride 68 (bank=4r+c), V stride 72 (bank=8c+r).
// No per-element cvt (Q/K/V pre-rounded to tf32 by producer).
// ---------------------------------------------------------------------------
#define QS 68
#define KS 68
#define VS 72
#define PS 68
#define OFF_Q 0
#define OFF_K (64 * QS)                       // + bf * 64*KS
#define OFF_V (OFF_K + 2 * 64 * KS)           // + bf * 64*VS
#define OFF_P (OFF_V + 2 * 64 * VS)
#define ASMEM_FLOATS (OFF_P + 64 * PS)
#define ASMEM_BYTES (ASMEM_FLOATS * 4)        // 106496 B

__global__ __launch_bounds__(128, 2)
void attn_mma()
{
    extern __shared__ float smf[];
    const uint32_t sb = smem_u32(smf);

    const int qb = blockIdx.x * 64;
    const int h  = blockIdx.y;
    const int b  = blockIdx.z;
    const float* Qp = g_Q + (size_t)((b * NH + h) * SEQ) * DK;
    const float* Kp = g_K + (size_t)((b * NH + h) * SEQ) * DK;
    const float* Vp = g_V + (size_t)((b * NH + h) * SEQ) * DK;
    const __half* Bh = g_biash + (size_t)(b * NH + h) * SEQ * SEQ;

    const int tid = threadIdx.x;
    const int lane = tid & 31, wid = tid >> 5;
    const int r = lane >> 2, c = lane & 3;
    const int q0 = wid * 16;

    const int row = tid >> 1;          // 0..63
    const int co  = (tid & 1) * 32;    // 0 / 32

    // ---- prologue: Q tile + K/V tile 0 (group G0) ----
    {
        const float* Qg = Qp + (size_t)(qb + row) * DK + co;
        const uint32_t qs = sb + (uint32_t)(OFF_Q + row * QS + co) * 4;
        #pragma unroll
        for (int j = 0; j < 8; j++) cp_async16(qs + j * 16, Qg + j * 4);
        const float* Kg = Kp + (size_t)row * DK + co;
        const float* Vg = Vp + (size_t)row * DK + co;
        const uint32_t ks_ = sb + (uint32_t)(OFF_K + row * KS + co) * 4;
        const uint32_t vs_ = sb + (uint32_t)(OFF_V + row * VS + co) * 4;
        #pragma unroll
        for (int j = 0; j < 8; j++) {
            cp_async16(ks_ + j * 16, Kg + j * 4);
            cp_async16(vs_ + j * 16, Vg + j * 4);
        }
        cp_commit();
    }

    float oAcc[8][4];
    #pragma unroll
    for (int dt = 0; dt < 8; dt++)
        #pragma unroll
        for (int j = 0; j < 4; j++) oAcc[dt][j] = 0.f;
    float mA = -1e30f, mB = -1e30f, lA = 0.f, lB = 0.f;

    for (int kt = 0; kt < 16; kt++) {
        // issue next tile into the other buffer
        if (kt < 15) {
            const int bf2 = (kt + 1) & 1;
            const float* Kg = Kp + (size_t)((kt + 1) * 64 + row) * DK + co;
            const float* Vg = Vp + (size_t)((kt + 1) * 64 + row) * DK + co;
            const uint32_t ks_ = sb + (uint32_t)(OFF_K + bf2 * 64 * KS + row * KS + co) * 4;
            const uint32_t vs_ = sb + (uint32_t)(OFF_V + bf2 * 64 * VS + row * VS + co) * 4;
            #pragma unroll
            for (int j = 0; j < 8; j++) {
                cp_async16(ks_ + j * 16, Kg + j * 4);
                cp_async16(vs_ + j * 16, Vg + j * 4);
            }
        }
        cp_commit();
        cp_wait1();            // tile kt (and Q) resident
        __syncthreads();

        const int bf = kt & 1;
        const int kb = kt * 64;
        const float* Qsf = smf + OFF_Q;
        const float* Ksf = smf + OFF_K + bf * 64 * KS;
        const float* Vsf = smf + OFF_V + bf * 64 * VS;
        float* Pr = smf + OFF_P;

        // bias prefetch (fp16, mask pre-folded)
        float2 bzA[8], bzB[8];
        {
            const __half2* BpA = (const __half2*)(Bh + (size_t)(qb + q0 + r) * SEQ + kb);
            const __half2* BpB = (const __half2*)(Bh + (size_t)(qb + q0 + r + 8) * SEQ + kb);
            #pragma unroll
            for (int nt = 0; nt < 8; nt++) {
                bzA[nt] = __half22float2(BpA[nt * 4 + c]);
                bzB[nt] = __half22float2(BpB[nt * 4 + c]);
            }
        }

        // ---- S = Q K^T ----
        float sAcc[8][4];
        #pragma unroll
        for (int nt = 0; nt < 8; nt++)
            #pragma unroll
            for (int j = 0; j < 4; j++) sAcc[nt][j] = 0.f;
        #pragma unroll
        for (int ks = 0; ks < 8; ks++) {
            const int kc = ks * 8 + c;
            uint32_t af[4];
            af[0] = __float_as_uint(Qsf[(q0 + r) * QS + kc]);
            af[1] = __float_as_uint(Qsf[(q0 + r + 8) * QS + kc]);
            af[2] = __float_as_uint(Qsf[(q0 + r) * QS + kc + 4]);
            af[3] = __float_as_uint(Qsf[(q0 + r + 8) * QS + kc + 4]);
            #pragma unroll
            for (int nt = 0; nt < 8; nt++) {
                uint32_t bfr[2];
                bfr[0] = __float_as_uint(Ksf[(nt * 8 + r) * KS + kc]);
                bfr[1] = __float_as_uint(Ksf[(nt * 8 + r) * KS + kc + 4]);
                mma_tf32(sAcc[nt], af, bfr);
            }
        }

        // ---- scale + bias, row max ----
        float mxA = -1e30f, mxB = -1e30f;
        #pragma unroll
        for (int nt = 0; nt < 8; nt++) {
            sAcc[nt][0] = fmaf(sAcc[nt][0], 0.125f, bzA[nt].x);
            sAcc[nt][1] = fmaf(sAcc[nt][1], 0.125f, bzA[nt].y);
            sAcc[nt][2] = fmaf(sAcc[nt][2], 0.125f, bzB[nt].x);
            sAcc[nt][3] = fmaf(sAcc[nt][3], 0.125f, bzB[nt].y);
            mxA = fmaxf(mxA, fmaxf(sAcc[nt][0], sAcc[nt][1]));
            mxB = fmaxf(mxB, fmaxf(sAcc[nt][2], sAcc[nt][3]));
        }
        mxA = fmaxf(mxA, __shfl_xor_sync(0xffffffffu, mxA, 1));
        mxA = fmaxf(mxA, __shfl_xor_sync(0xffffffffu, mxA, 2));
        mxB = fmaxf(mxB, __shfl_xor_sync(0xffffffffu, mxB, 1));
        mxB = fmaxf(mxB, __shfl_xor_sync(0xffffffffu, mxB, 2));

        const float mnA = fmaxf(mA, mxA);
        const float mnB = fmaxf(mB, mxB);
        float sumA = 0.f, sumB = 0.f;
        #pragma unroll
        for (int nt = 0; nt < 8; nt++) {
            float p0 = __expf(sAcc[nt][0] - mnA);
            float p1 = __expf(sAcc[nt][1] - mnA);
            float p2 = __expf(sAcc[nt][2] - mnB);
            float p3 = __expf(sAcc[nt][3] - mnB);
            sumA += p0 + p1;
            sumB += p2 + p3;
            float2 pa = { to_tf32(p0), to_tf32(p1) };
            float2 pb = { to_tf32(p2), to_tf32(p3) };
            *(float2*)&Pr[(q0 + r) * PS + nt * 8 + 2 * c] = pa;
            *(float2*)&Pr[(q0 + r + 8) * PS + nt * 8 + 2 * c] = pb;
        }
        sumA += __shfl_xor_sync(0xffffffffu, sumA, 1);
        sumA += __shfl_xor_sync(0xffffffffu, sumA, 2);
        sumB += __shfl_xor_sync(0xffffffffu, sumB, 1);
        sumB += __shfl_xor_sync(0xffffffffu, sumB, 2);

        const float sclA = __expf(mA - mnA);
        const float sclB = __expf(mB - mnB);
        lA = lA * sclA + sumA;  mA = mnA;
        lB = lB * sclB + sumB;  mB = mnB;
        #pragma unroll
        for (int dt = 0; dt < 8; dt++) {
            oAcc[dt][0] *= sclA;  oAcc[dt][1] *= sclA;
            oAcc[dt][2] *= sclB;  oAcc[dt][3] *= sclB;
        }
        __syncwarp();

        // ---- O += P V ----
        #pragma unroll
        for (int ks = 0; ks < 8; ks++) {
            const int kc = ks * 8 + c;
            uint32_t af[4];
            af[0] = __float_as_uint(Pr[(q0 + r) * PS + kc]);
            af[1] = __float_as_uint(Pr[(q0 + r + 8) * PS + kc]);
            af[2] = __float_as_uint(Pr[(q0 + r) * PS + kc + 4]);
            af[3] = __float_as_uint(Pr[(q0 + r + 8) * PS + kc + 4]);
            #pragma unroll
            for (int dt = 0; dt < 8; dt++) {
                uint32_t bfr[2];
                bfr[0] = __float_as_uint(Vsf[kc * VS + dt * 8 + r]);
                bfr[1] = __float_as_uint(Vsf[(kc + 4) * VS + dt * 8 + r]);
                mma_tf32(oAcc[dt], af, bfr);
            }
        }
        __syncthreads();   // all warps done with buffer kt before it is refilled
    }

    // ---- normalize + write ctx[b, s, h*64 + d] ----
    const float iA = 1.f / lA;
    const float iB = 1.f / lB;
    float* Op = g_ctx + (size_t)(b * SEQ + qb + q0 + r) * DMODEL + h * 64 + 2 * c;
    #pragma unroll
    for (int dt = 0; dt < 8; dt++) {
        float2 vA = { oAcc[dt][0] * iA, oAcc[dt][1] * iA };
        float2 vB = { oAcc[dt][2] * iB, oAcc[dt][3] * iB };
        *(float2*)(Op + dt * 8) = vA;
        *(float2*)(Op + 8 * DMODEL + dt * 8) = vB;
    }
}

// ---------------------------------------------------------------------------
extern "C" void kernel_launch(void* const* d_in, const int* in_sizes, int n_in,
                              void* d_out, int out_size)
{
    const float* x    = (const float*)d_in[0];
    const float* geom = (const float*)d_in[1];
    const int*   mask = (const int*)d_in[2];
    const float* Wq = (const float*)d_in[3];
    const float* bq = (const float*)d_in[4];
    const float* Wk = (const float*)d_in[5];
    const float* bk = (const float*)d_in[6];
    const float* Wv = (const float*)d_in[7];
    const float* bv = (const float*)d_in[8];
    const float* Wo = (const float*)d_in[9];
    const float* bo = (const float*)d_in[10];
    const float* Wg = (const float*)d_in[11];
    const float* bg = (const float*)d_in[12];
    float* out = (float*)d_out;

    cudaFuncSetAttribute(gemm_mma, cudaFuncAttributeMaxDynamicSharedMemorySize, GSMEM_BYTES);
    cudaFuncSetAttribute(attn_mma, cudaFuncAttributeMaxDynamicSharedMemorySize, ASMEM_BYTES);

    // QKV projections (epilogue tf32-rounds into g_Q/g_K/g_V)
    gemm_mma<<<dim3(24, 32), 256, GSMEM_BYTES>>>(x, Wq, Wk, Wv, bq, bk, bv, nullptr, 0);

    // geometric bias (fp16, mask folded)
    geom_bias_kernel<<<(BATCH * SEQ * SEQ) / 256, 256>>>(geom, Wg, bg, mask);

    // attention
    attn_mma<<<dim3(SEQ / 64, NH, BATCH), 128, ASMEM_BYTES>>>();

    // output projection
    gemm_mma<<<dim3(8, 32), 256, GSMEM_BYTES>>>(nullptr, Wo, nullptr, nullptr, bo, nullptr, nullptr, out, 1);
}

// round 7
// speedup vs baseline: 2.0250x; 2.0250x over previous
#include <cuda_runtime.h>
#include <cuda_fp16.h>
#include <math.h>
#include <cstdint>

#define BATCH  4
#define SEQ    1024
#define DMODEL 1024
#define NH     16
#define DK     64

// ---------------- scratch (device globals: allocation-free) ----------------
__device__ __half g_xh[BATCH * SEQ * DMODEL];
__device__ __half g_WTh[4 * 1024 * 1024];     // W^T per matrix: [n][k] fp16
__device__ __half g_Qh[BATCH * NH * SEQ * DK];
__device__ __half g_Kh[BATCH * NH * SEQ * DK];
__device__ __half g_Vh[BATCH * NH * SEQ * DK];
__device__ __half g_ctxh[BATCH * SEQ * DMODEL];
__device__ __half g_biash[(size_t)BATCH * NH * SEQ * SEQ];  // 134 MB, mask folded

// ---------------- helpers ----------------
__device__ __forceinline__ void mma_f16(float c[4], const uint32_t a[4], const uint32_t b[2]) {
    asm volatile("mma.sync.aligned.m16n8k16.row.col.f32.f16.f16.f32 "
                 "{%0,%1,%2,%3}, {%4,%5,%6,%7}, {%8,%9}, {%0,%1,%2,%3};"
                 : "+f"(c[0]), "+f"(c[1]), "+f"(c[2]), "+f"(c[3])
                 : "r"(a[0]), "r"(a[1]), "r"(a[2]), "r"(a[3]), "r"(b[0]), "r"(b[1]));
}
__device__ __forceinline__ uint32_t smem_u32(const void* p) {
    uint32_t a;
    asm("{ .reg .u64 t; cvta.to.shared.u64 t, %1; cvt.u32.u64 %0, t; }" : "=r"(a) : "l"(p));
    return a;
}
__device__ __forceinline__ void cp_async16(uint32_t s, const void* g) {
    asm volatile("cp.async.cg.shared.global [%0], [%1], 16;" :: "r"(s), "l"(g) : "memory");
}
__device__ __forceinline__ void cp_commit() {
    asm volatile("cp.async.commit_group;" ::: "memory");
}
__device__ __forceinline__ void cp_wait1() {
    asm volatile("cp.async.wait_group 1;" ::: "memory");
}
__device__ __forceinline__ void ldsm_x4(uint32_t& d0, uint32_t& d1, uint32_t& d2, uint32_t& d3,
                                        uint32_t addr) {
    asm volatile("ldmatrix.sync.aligned.m8n8.x4.shared.b16 {%0,%1,%2,%3}, [%4];"
                 : "=r"(d0), "=r"(d1), "=r"(d2), "=r"(d3) : "r"(addr));
}
__device__ __forceinline__ void ldsm_x4_t(uint32_t& d0, uint32_t& d1, uint32_t& d2, uint32_t& d3,
                                          uint32_t addr) {
    asm volatile("ldmatrix.sync.aligned.m8n8.x4.trans.shared.b16 {%0,%1,%2,%3}, [%4];"
                 : "=r"(d0), "=r"(d1), "=r"(d2), "=r"(d3) : "r"(addr));
}
__device__ __forceinline__ uint32_t pack_h2(float lo, float hi) {
    __half2 h = __floats2half2_rn(lo, hi);
    return *(uint32_t*)&h;
}

// ---------------------------------------------------------------------------
// Input conversion: x (fp32) -> g_xh (fp16)
// ---------------------------------------------------------------------------
__global__ void convert_x(const float* __restrict__ x)
{
    size_t i = ((size_t)blockIdx.x * 256 + threadIdx.x) * 4;
    float4 v = *(const float4*)(x + i);
    uint32_t u0 = pack_h2(v.x, v.y);
    uint32_t u1 = pack_h2(v.z, v.w);
    *(uint32_t*)&g_xh[i] = u0;
    *(uint32_t*)&g_xh[i + 2] = u1;
}

// ---------------------------------------------------------------------------
// Weight transpose + convert: g_WTh[mat][n][k] = half(W[k][n])
// ---------------------------------------------------------------------------
__global__ void transpose_w_h(const float* __restrict__ W0, const float* __restrict__ W1,
                              const float* __restrict__ W2, const float* __restrict__ W3)
{
    __shared__ float t[32][33];
    const float* W = (blockIdx.z == 0) ? W0 : (blockIdx.z == 1) ? W1
                   : (blockIdx.z == 2) ? W2 : W3;
    __half* Wt = g_WTh + (size_t)blockIdx.z * 1024 * 1024;
    int bx = blockIdx.x * 32, by = blockIdx.y * 32;
    int tx = threadIdx.x, ty = threadIdx.y;
    #pragma unroll
    for (int i = 0; i < 32; i += 8)
        t[ty + i][tx] = W[(size_t)(by + ty + i) * 1024 + bx + tx];
    __syncthreads();
    #pragma unroll
    for (int i = 0; i < 32; i += 8)
        Wt[(size_t)(bx + ty + i) * 1024 + by + tx] = __float2half(t[tx][ty + i]);
}

// ---------------------------------------------------------------------------
// fp16 GEMM (m16n8k16): C[M,N] = A @ W + bias.  CTA 128x128, k-slab 32,
// cp.async double-buffered.  mode 0: QKV fused -> g_{Q,K,V}h [b,h,s,dk] fp16.
// mode 1: outproj (A = g_ctxh) -> fp32 Cout.
// ---------------------------------------------------------------------------
#define GST 40                                   // smem row stride (halfs)
#define GBUFH (2 * 128 * GST)                    // halfs per buffer (A+B)
#define GSMEM_BYTES (2 * GBUFH * 2)              // 40960 B

__global__ __launch_bounds__(256)
void gemm_h(const float* __restrict__ bias0, const float* __restrict__ bias1,
            const float* __restrict__ bias2, float* __restrict__ Cout, int mode)
{
    extern __shared__ __half smh[];
    const uint32_t sb = smem_u32(smh);
    const int tid = threadIdx.x, lane = tid & 31;
    const int wid = tid >> 5;
    const int wm = wid & 3, wn = wid >> 2;
    const int r = lane >> 2, c = lane & 3;

    int mat, bn;
    const float* bias;
    if (mode == 0) {
        mat = blockIdx.x >> 3;
        bn = (blockIdx.x & 7) * 128;
        bias = (mat == 0) ? bias0 : (mat == 1) ? bias1 : bias2;
    } else {
        mat = 3;
        bn = blockIdx.x * 128;
        bias = bias0;
    }
    const int bm = blockIdx.y * 128;
    const __half* Ah = (mode == 0) ? g_xh : g_ctxh;
    const __half* Bh = g_WTh + (size_t)mat * 1024 * 1024;

    const int row = tid >> 1;            // 0..127
    const int off = (tid & 1) * 16;      // halfs

    const __half* Ag0 = Ah + (size_t)(bm + row) * 1024 + off;
    const __half* Bg0 = Bh + (size_t)(bn + row) * 1024 + off;

    // prologue: slab 0 -> buf 0
    {
        uint32_t ad = sb + (uint32_t)(row * GST + off) * 2;
        uint32_t bd = sb + (uint32_t)(128 * GST + row * GST + off) * 2;
        cp_async16(ad, Ag0);       cp_async16(ad + 16, Ag0 + 8);
        cp_async16(bd, Bg0);       cp_async16(bd + 16, Bg0 + 8);
        cp_commit();
    }

    float acc[2][8][4];
    #pragma unroll
    for (int im = 0; im < 2; im++)
        #pragma unroll
        for (int nt = 0; nt < 8; nt++)
            #pragma unroll
            for (int j = 0; j < 4; j++) acc[im][nt][j] = 0.f;

    for (int s = 0; s < 32; s++) {
        if (s < 31) {
            const int buf = (s + 1) & 1;
            const int k0 = (s + 1) * 32;
            uint32_t ad = sb + (uint32_t)(buf * GBUFH + row * GST + off) * 2;
            uint32_t bd = sb + (uint32_t)(buf * GBUFH + 128 * GST + row * GST + off) * 2;
            cp_async16(ad, Ag0 + k0);       cp_async16(ad + 16, Ag0 + k0 + 8);
            cp_async16(bd, Bg0 + k0);       cp_async16(bd + 16, Bg0 + k0 + 8);
        }
        cp_commit();
        cp_wait1();
        __syncthreads();

        const __half* Ab = smh + (s & 1) * GBUFH;
        const __half* Bb = Ab + 128 * GST;
        #pragma unroll
        for (int ks = 0; ks < 2; ks++) {
            uint32_t af[2][4];
            #pragma unroll
            for (int im = 0; im < 2; im++) {
                const int m0 = wm * 32 + im * 16;
                af[im][0] = *(const uint32_t*)&Ab[(m0 + r) * GST + ks * 16 + 2 * c];
                af[im][1] = *(const uint32_t*)&Ab[(m0 + r + 8) * GST + ks * 16 + 2 * c];
                af[im][2] = *(const uint32_t*)&Ab[(m0 + r) * GST + ks * 16 + 2 * c + 8];
                af[im][3] = *(const uint32_t*)&Ab[(m0 + r + 8) * GST + ks * 16 + 2 * c + 8];
            }
            #pragma unroll
            for (int nt = 0; nt < 8; nt++) {
                const int n0 = wn * 64 + nt * 8;
                uint32_t bf[2];
                bf[0] = *(const uint32_t*)&Bb[(n0 + r) * GST + ks * 16 + 2 * c];
                bf[1] = *(const uint32_t*)&Bb[(n0 + r) * GST + ks * 16 + 2 * c + 8];
                mma_f16(acc[0][nt], af[0], bf);
                mma_f16(acc[1][nt], af[1], bf);
            }
        }
        __syncthreads();
    }

    // epilogue
    #pragma unroll
    for (int im = 0; im < 2; im++) {
        #pragma unroll
        for (int nt = 0; nt < 8; nt++) {
            const int m = bm + wm * 32 + im * 16 + r;
            const int n = bn + wn * 64 + nt * 8 + 2 * c;
            float2 bz = *(const float2*)&bias[n];
            float v00 = acc[im][nt][0] + bz.x, v01 = acc[im][nt][1] + bz.y;
            float v10 = acc[im][nt][2] + bz.x, v11 = acc[im][nt][3] + bz.y;
            if (mode == 0) {
                const int bb = m >> 10, ss = m & 1023;
                const int hh = n >> 6, dd = n & 63;
                __half* dst = ((mat == 0) ? g_Qh : (mat == 1) ? g_Kh : g_Vh)
                            + ((size_t)((bb * NH + hh) * SEQ + ss)) * DK + dd;
                *(uint32_t*)dst = pack_h2(v00, v01);
                *(uint32_t*)(dst + 8 * DK) = pack_h2(v10, v11);
            } else {
                float* dst = Cout + (size_t)m * 1024 + n;
                float2 a0 = { v00, v01 }, a1 = { v10, v11 };
                *(float2*)dst = a0;
                *(float2*)(dst + 8 * 1024) = a1;
            }
        }
    }
}

// ---------------------------------------------------------------------------
// Geometry bias (fp16, mask folded)
// ---------------------------------------------------------------------------
__global__ __launch_bounds__(256)
void geom_bias_kernel(const float* __restrict__ geom, const float* __restrict__ Wg,
                      const float* __restrict__ bg, const int* __restrict__ mask)
{
    __shared__ float wgs[7][16];
    __shared__ float bgs[16];
    int tid = threadIdx.x;
    if (tid < 112) wgs[tid / 16][tid % 16] = Wg[tid];
    if (tid < 16)  bgs[tid] = bg[tid];
    __syncthreads();

    size_t idx = (size_t)blockIdx.x * 256 + tid;
    const float* gp = geom + idx * 7;
    float g[7];
    #pragma unroll
    for (int i = 0; i < 7; i++) g[i] = gp[i];

    int k = (int)(idx & 1023);
    int bq = (int)(idx >> 10);
    int q = bq & 1023;
    int b = bq >> 10;
    const bool live = mask[b * SEQ + k] != 0;
    size_t base = ((size_t)(b * NH) * SEQ + q) * SEQ + k;

    #pragma unroll
    for (int h = 0; h < NH; h++) {
        float v = bgs[h];
        #pragma unroll
        for (int i = 0; i < 7; i++) v += g[i] * wgs[i][h];
        g_biash[base + (size_t)h * SEQ * SEQ] = __float2half(live ? v : -30000.f);
    }
}

// ---------------------------------------------------------------------------
// fp16 flash attention: 128 thr / 4 warps, q-tile 64, m16n8k16.
// Q fragments in registers (loaded once).  K frags: ldmatrix.x4.
// V frags: ldmatrix.x4.trans.  P: register half2 conversion, no smem.
// K/V/bias cp.async double-buffered.  stride 72 halfs (conflict-free).
// ---------------------------------------------------------------------------
#define AVS 72
#define TILEH (64 * AVS)                           // 4608 halfs per tile
#define AOFF_K(buf) ((buf) * TILEH)
#define AOFF_V(buf) (2 * TILEH + (buf) * TILEH)
#define AOFF_B(buf) (4 * TILEH + (buf) * TILEH)
#define ASMEM_BYTES (6 * TILEH * 2)                // 55296 B

__global__ __launch_bounds__(128, 4)
void attn_h()
{
    extern __shared__ __half smh[];
    const uint32_t sb = smem_u32(smh);

    const int qb = blockIdx.x * 64;
    const int h  = blockIdx.y;
    const int b  = blockIdx.z;
    const __half* Qp = g_Qh + (size_t)((b * NH + h) * SEQ) * DK;
    const __half* Kp = g_Kh + (size_t)((b * NH + h) * SEQ) * DK;
    const __half* Vp = g_Vh + (size_t)((b * NH + h) * SEQ) * DK;
    const __half* Bp = g_biash + (size_t)(b * NH + h) * SEQ * SEQ;

    const int tid = threadIdx.x;
    const int lane = tid & 31, wid = tid >> 5;
    const int r = lane >> 2, c = lane & 3;
    const int q0 = wid * 16;

    const int row = tid >> 1;              // 0..63
    const int off = (tid & 1) * 32;        // halfs

    // Q fragments: 4 ks-blocks x 4 regs, resident for the whole kernel
    uint32_t qf[4][4];
    {
        const __half* qr0 = Qp + (size_t)(qb + q0 + r) * DK;
        const __half* qr1 = Qp + (size_t)(qb + q0 + r + 8) * DK;
        #pragma unroll
        for (int ks = 0; ks < 4; ks++) {
            qf[ks][0] = *(const uint32_t*)&qr0[ks * 16 + 2 * c];
            qf[ks][1] = *(const uint32_t*)&qr1[ks * 16 + 2 * c];
            qf[ks][2] = *(const uint32_t*)&qr0[ks * 16 + 2 * c + 8];
            qf[ks][3] = *(const uint32_t*)&qr1[ks * 16 + 2 * c + 8];
        }
    }

    // prologue: tile 0
    {
        const __half* Kg = Kp + (size_t)row * DK + off;
        const __half* Vg = Vp + (size_t)row * DK + off;
        const __half* Bg = Bp + (size_t)(qb + row) * SEQ + off;
        uint32_t kd = sb + (uint32_t)(AOFF_K(0) + row * AVS + off) * 2;
        uint32_t vd = sb + (uint32_t)(AOFF_V(0) + row * AVS + off) * 2;
        uint32_t bd = sb + (uint32_t)(AOFF_B(0) + row * AVS + off) * 2;
        #pragma unroll
        for (int j = 0; j < 4; j++) {
            cp_async16(kd + j * 16, Kg + j * 8);
            cp_async16(vd + j * 16, Vg + j * 8);
            cp_async16(bd + j * 16, Bg + j * 8);
        }
        cp_commit();
    }

    float oAcc[8][4];
    #pragma unroll
    for (int dt = 0; dt < 8; dt++)
        #pragma unroll
        for (int j = 0; j < 4; j++) oAcc[dt][j] = 0.f;
    float mA = -1e30f, mB = -1e30f, lA = 0.f, lB = 0.f;

    for (int kt = 0; kt < 16; kt++) {
        if (kt < 15) {
            const int buf = (kt + 1) & 1;
            const int kb2 = (kt + 1) * 64;
            const __half* Kg = Kp + (size_t)(kb2 + row) * DK + off;
            const __half* Vg = Vp + (size_t)(kb2 + row) * DK + off;
            const __half* Bg = Bp + (size_t)(qb + row) * SEQ + kb2 + off;
            uint32_t kd = sb + (uint32_t)(AOFF_K(buf) + row * AVS + off) * 2;
            uint32_t vd = sb + (uint32_t)(AOFF_V(buf) + row * AVS + off) * 2;
            uint32_t bd = sb + (uint32_t)(AOFF_B(buf) + row * AVS + off) * 2;
            #pragma unroll
            for (int j = 0; j < 4; j++) {
                cp_async16(kd + j * 16, Kg + j * 8);
                cp_async16(vd + j * 16, Vg + j * 8);
                cp_async16(bd + j * 16, Bg + j * 8);
            }
        }
        cp_commit();
        cp_wait1();
        __syncthreads();

        const int buf = kt & 1;
        const uint32_t kbase = sb + (uint32_t)AOFF_K(buf) * 2;
        const uint32_t vbase = sb + (uint32_t)AOFF_V(buf) * 2;
        const __half* Bsm = smh + AOFF_B(buf);

        // ---- S = Q K^T ----
        float sAcc[8][4];
        #pragma unroll
        for (int nt = 0; nt < 8; nt++)
            #pragma unroll
            for (int j = 0; j < 4; j++) sAcc[nt][j] = 0.f;

        const int kmat = lane >> 3;           // which 8x8 matrix this lane addresses
        const int krow_in = lane & 7;
        #pragma unroll
        for (int ks = 0; ks < 4; ks++) {
            #pragma unroll
            for (int ntp = 0; ntp < 4; ntp++) {
                const int seqrow = ntp * 16 + ((kmat >> 1) & 1) * 8 + krow_in;
                const int col = ks * 16 + (kmat & 1) * 8;
                uint32_t addr = kbase + (uint32_t)(seqrow * AVS + col) * 2;
                uint32_t d0, d1, d2, d3;
                ldsm_x4(d0, d1, d2, d3, addr);
                uint32_t b01[2] = { d0, d1 };
                uint32_t b23[2] = { d2, d3 };
                mma_f16(sAcc[2 * ntp],     qf[ks], b01);
                mma_f16(sAcc[2 * ntp + 1], qf[ks], b23);
            }
        }

        // ---- scale + bias (smem, mask pre-folded), row max ----
        float mxA = -1e30f, mxB = -1e30f;
        #pragma unroll
        for (int nt = 0; nt < 8; nt++) {
            uint32_t uA = *(const uint32_t*)&Bsm[(q0 + r) * AVS + nt * 8 + 2 * c];
            uint32_t uB = *(const uint32_t*)&Bsm[(q0 + r + 8) * AVS + nt * 8 + 2 * c];
            float2 bzA = __half22float2(*(__half2*)&uA);
            float2 bzB = __half22float2(*(__half2*)&uB);
            sAcc[nt][0] = fmaf(sAcc[nt][0], 0.125f, bzA.x);
            sAcc[nt][1] = fmaf(sAcc[nt][1], 0.125f, bzA.y);
            sAcc[nt][2] = fmaf(sAcc[nt][2], 0.125f, bzB.x);
            sAcc[nt][3] = fmaf(sAcc[nt][3], 0.125f, bzB.y);
            mxA = fmaxf(mxA, fmaxf(sAcc[nt][0], sAcc[nt][1]));
            mxB = fmaxf(mxB, fmaxf(sAcc[nt][2], sAcc[nt][3]));
        }
        mxA = fmaxf(mxA, __shfl_xor_sync(0xffffffffu, mxA, 1));
        mxA = fmaxf(mxA, __shfl_xor_sync(0xffffffffu, mxA, 2));
        mxB = fmaxf(mxB, __shfl_xor_sync(0xffffffffu, mxB, 1));
        mxB = fmaxf(mxB, __shfl_xor_sync(0xffffffffu, mxB, 2));

        const float mnA = fmaxf(mA, mxA);
        const float mnB = fmaxf(mB, mxB);
        float sumA = 0.f, sumB = 0.f;
        #pragma unroll
        for (int nt = 0; nt < 8; nt++) {
            sAcc[nt][0] = __expf(sAcc[nt][0] - mnA);
            sAcc[nt][1] = __expf(sAcc[nt][1] - mnA);
            sAcc[nt][2] = __expf(sAcc[nt][2] - mnB);
            sAcc[nt][3] = __expf(sAcc[nt][3] - mnB);
            sumA += sAcc[nt][0] + sAcc[nt][1];
            sumB += sAcc[nt][2] + sAcc[nt][3];
        }
        sumA += __shfl_xor_sync(0xffffffffu, sumA, 1);
        sumA += __shfl_xor_sync(0xffffffffu, sumA, 2);
        sumB += __shfl_xor_sync(0xffffffffu, sumB, 1);
        sumB += __shfl_xor_sync(0xffffffffu, sumB, 2);

        const float sclA = __expf(mA - mnA);
        const float sclB = __expf(mB - mnB);
        lA = lA * sclA + sumA;  mA = mnA;
        lB = lB * sclB + sumB;  mB = mnB;
        #pragma unroll
        for (int dt = 0; dt < 8; dt++) {
            oAcc[dt][0] *= sclA;  oAcc[dt][1] *= sclA;
            oAcc[dt][2] *= sclB;  oAcc[dt][3] *= sclB;
        }

        // ---- O += P V  (P as register A-frags, V via ldmatrix.trans) ----
        #pragma unroll
        for (int ks = 0; ks < 4; ks++) {
            uint32_t pa[4];
            pa[0] = pack_h2(sAcc[2 * ks][0],     sAcc[2 * ks][1]);
            pa[1] = pack_h2(sAcc[2 * ks][2],     sAcc[2 * ks][3]);
            pa[2] = pack_h2(sAcc[2 * ks + 1][0], sAcc[2 * ks + 1][1]);
            pa[3] = pack_h2(sAcc[2 * ks + 1][2], sAcc[2 * ks + 1][3]);
            #pragma unroll
            for (int dtp = 0; dtp < 4; dtp++) {
                const int vrow = ks * 16 + (kmat & 1) * 8 + krow_in;
                const int vcol = dtp * 16 + ((kmat >> 1) & 1) * 8;
                uint32_t addr = vbase + (uint32_t)(vrow * AVS + vcol) * 2;
                uint32_t d0, d1, d2, d3;
                ldsm_x4_t(d0, d1, d2, d3, addr);
                uint32_t b01[2] = { d0, d1 };
                uint32_t b23[2] = { d2, d3 };
                mma_f16(oAcc[2 * dtp],     pa, b01);
                mma_f16(oAcc[2 * dtp + 1], pa, b23);
            }
        }
        __syncthreads();
    }

    // ---- normalize + write ctx (fp16) ----
    const float iA = 1.f / lA;
    const float iB = 1.f / lB;
    __half* Op0 = g_ctxh + (size_t)(b * SEQ + qb + q0 + r) * DMODEL + h * 64 + 2 * c;
    __half* Op1 = Op0 + (size_t)8 * DMODEL;
    #pragma unroll
    for (int dt = 0; dt < 8; dt++) {
        *(uint32_t*)(Op0 + dt * 8) = pack_h2(oAcc[dt][0] * iA, oAcc[dt][1] * iA);
        *(uint32_t*)(Op1 + dt * 8) = pack_h2(oAcc[dt][2] * iB, oAcc[dt][3] * iB);
    }
}

// ---------------------------------------------------------------------------
extern "C" void kernel_launch(void* const* d_in, const int* in_sizes, int n_in,
                              void* d_out, int out_size)
{
    const float* x    = (const float*)d_in[0];
    const float* geom = (const float*)d_in[1];
    const int*   mask = (const int*)d_in[2];
    const float* Wq = (const float*)d_in[3];
    const float* bq = (const float*)d_in[4];
    const float* Wk = (const float*)d_in[5];
    const float* bk = (const float*)d_in[6];
    const float* Wv = (const float*)d_in[7];
    const float* bv = (const float*)d_in[8];
    const float* Wo = (const float*)d_in[9];
    const float* bo = (const float*)d_in[10];
    const float* Wg = (const float*)d_in[11];
    const float* bg = (const float*)d_in[12];
    float* out = (float*)d_out;

    cudaFuncSetAttribute(gemm_h, cudaFuncAttributeMaxDynamicSharedMemorySize, GSMEM_BYTES);
    cudaFuncSetAttribute(attn_h, cudaFuncAttributeMaxDynamicSharedMemorySize, ASMEM_BYTES);

    convert_x<<<(BATCH * SEQ * DMODEL) / (256 * 4), 256>>>(x);
    transpose_w_h<<<dim3(32, 32, 4), dim3(32, 8)>>>(Wq, Wk, Wv, Wo);

    gemm_h<<<dim3(24, 32), 256, GSMEM_BYTES>>>(bq, bk, bv, nullptr, 0);

    geom_bias_kernel<<<(BATCH * SEQ * SEQ) / 256, 256>>>(geom, Wg, bg, mask);

    attn_h<<<dim3(SEQ / 64, NH, BATCH), 128, ASMEM_BYTES>>>();

    gemm_h<<<dim3(8, 32), 256, GSMEM_BYTES>>>(bo, nullptr, nullptr, out, 1);
}

// round 8
// speedup vs baseline: 2.1468x; 1.0601x over previous
#include <cuda_runtime.h>
#include <cuda_fp16.h>
#include <math.h>
#include <cstdint>

#define BATCH  4
#define SEQ    1024
#define DMODEL 1024
#define NH     16
#define DK     64

// ---------------- scratch (device globals: allocation-free) ----------------
__device__ __half g_xh[BATCH * SEQ * DMODEL];
__device__ __half g_WTh[4 * 1024 * 1024];     // W^T per matrix: [n][k] fp16
__device__ __half g_Qh[BATCH * NH * SEQ * DK];
__device__ __half g_Kh[BATCH * NH * SEQ * DK];
__device__ __half g_Vh[BATCH * NH * SEQ * DK];
__device__ __half g_ctxh[BATCH * SEQ * DMODEL];
__device__ __half g_biash[(size_t)BATCH * NH * SEQ * SEQ];  // 134 MB, mask folded

// ---------------- helpers ----------------
__device__ __forceinline__ void mma_f16(float c[4], const uint32_t a[4], const uint32_t b[2]) {
    asm volatile("mma.sync.aligned.m16n8k16.row.col.f32.f16.f16.f32 "
                 "{%0,%1,%2,%3}, {%4,%5,%6,%7}, {%8,%9}, {%0,%1,%2,%3};"
                 : "+f"(c[0]), "+f"(c[1]), "+f"(c[2]), "+f"(c[3])
                 : "r"(a[0]), "r"(a[1]), "r"(a[2]), "r"(a[3]), "r"(b[0]), "r"(b[1]));
}
__device__ __forceinline__ uint32_t smem_u32(const void* p) {
    uint32_t a;
    asm("{ .reg .u64 t; cvta.to.shared.u64 t, %1; cvt.u32.u64 %0, t; }" : "=r"(a) : "l"(p));
    return a;
}
__device__ __forceinline__ void cp_async16(uint32_t s, const void* g) {
    asm volatile("cp.async.cg.shared.global [%0], [%1], 16;" :: "r"(s), "l"(g) : "memory");
}
__device__ __forceinline__ void cp_commit() {
    asm volatile("cp.async.commit_group;" ::: "memory");
}
__device__ __forceinline__ void cp_wait1() {
    asm volatile("cp.async.wait_group 1;" ::: "memory");
}
__device__ __forceinline__ void ldsm_x4(uint32_t& d0, uint32_t& d1, uint32_t& d2, uint32_t& d3,
                                        uint32_t addr) {
    asm volatile("ldmatrix.sync.aligned.m8n8.x4.shared.b16 {%0,%1,%2,%3}, [%4];"
                 : "=r"(d0), "=r"(d1), "=r"(d2), "=r"(d3) : "r"(addr));
}
__device__ __forceinline__ void ldsm_x4_t(uint32_t& d0, uint32_t& d1, uint32_t& d2, uint32_t& d3,
                                          uint32_t addr) {
    asm volatile("ldmatrix.sync.aligned.m8n8.x4.trans.shared.b16 {%0,%1,%2,%3}, [%4];"
                 : "=r"(d0), "=r"(d1), "=r"(d2), "=r"(d3) : "r"(addr));
}
__device__ __forceinline__ uint32_t pack_h2(float lo, float hi) {
    __half2 h = __floats2half2_rn(lo, hi);
    return *(uint32_t*)&h;
}

// ---------------------------------------------------------------------------
// Input conversion: x (fp32) -> g_xh (fp16)
// ---------------------------------------------------------------------------
__global__ void convert_x(const float* __restrict__ x)
{
    size_t i = ((size_t)blockIdx.x * 256 + threadIdx.x) * 4;
    float4 v = *(const float4*)(x + i);
    *(uint32_t*)&g_xh[i] = pack_h2(v.x, v.y);
    *(uint32_t*)&g_xh[i + 2] = pack_h2(v.z, v.w);
}

// ---------------------------------------------------------------------------
// Weight transpose + convert: g_WTh[mat][n][k] = half(W[k][n])
// ---------------------------------------------------------------------------
__global__ void transpose_w_h(const float* __restrict__ W0, const float* __restrict__ W1,
                              const float* __restrict__ W2, const float* __restrict__ W3)
{
    __shared__ float t[32][33];
    const float* W = (blockIdx.z == 0) ? W0 : (blockIdx.z == 1) ? W1
                   : (blockIdx.z == 2) ? W2 : W3;
    __half* Wt = g_WTh + (size_t)blockIdx.z * 1024 * 1024;
    int bx = blockIdx.x * 32, by = blockIdx.y * 32;
    int tx = threadIdx.x, ty = threadIdx.y;
    #pragma unroll
    for (int i = 0; i < 32; i += 8)
        t[ty + i][tx] = W[(size_t)(by + ty + i) * 1024 + bx + tx];
    __syncthreads();
    #pragma unroll
    for (int i = 0; i < 32; i += 8)
        Wt[(size_t)(bx + ty + i) * 1024 + by + tx] = __float2half(t[tx][ty + i]);
}

// ---------------------------------------------------------------------------
// fp16 GEMM (m16n8k16), unchanged from R7.
// ---------------------------------------------------------------------------
#define GST 40
#define GBUFH (2 * 128 * GST)
#define GSMEM_BYTES (2 * GBUFH * 2)

__global__ __launch_bounds__(256)
void gemm_h(const float* __restrict__ bias0, const float* __restrict__ bias1,
            const float* __restrict__ bias2, float* __restrict__ Cout, int mode)
{
    extern __shared__ __half smh[];
    const uint32_t sb = smem_u32(smh);
    const int tid = threadIdx.x, lane = tid & 31;
    const int wid = tid >> 5;
    const int wm = wid & 3, wn = wid >> 2;
    const int r = lane >> 2, c = lane & 3;

    int mat, bn;
    const float* bias;
    if (mode == 0) {
        mat = blockIdx.x >> 3;
        bn = (blockIdx.x & 7) * 128;
        bias = (mat == 0) ? bias0 : (mat == 1) ? bias1 : bias2;
    } else {
        mat = 3;
        bn = blockIdx.x * 128;
        bias = bias0;
    }
    const int bm = blockIdx.y * 128;
    const __half* Ah = (mode == 0) ? g_xh : g_ctxh;
    const __half* Bh = g_WTh + (size_t)mat * 1024 * 1024;

    const int row = tid >> 1;
    const int off = (tid & 1) * 16;

    const __half* Ag0 = Ah + (size_t)(bm + row) * 1024 + off;
    const __half* Bg0 = Bh + (size_t)(bn + row) * 1024 + off;

    {
        uint32_t ad = sb + (uint32_t)(row * GST + off) * 2;
        uint32_t bd = sb + (uint32_t)(128 * GST + row * GST + off) * 2;
        cp_async16(ad, Ag0);       cp_async16(ad + 16, Ag0 + 8);
        cp_async16(bd, Bg0);       cp_async16(bd + 16, Bg0 + 8);
        cp_commit();
    }

    float acc[2][8][4];
    #pragma unroll
    for (int im = 0; im < 2; im++)
        #pragma unroll
        for (int nt = 0; nt < 8; nt++)
            #pragma unroll
            for (int j = 0; j < 4; j++) acc[im][nt][j] = 0.f;

    for (int s = 0; s < 32; s++) {
        if (s < 31) {
            const int buf = (s + 1) & 1;
            const int k0 = (s + 1) * 32;
            uint32_t ad = sb + (uint32_t)(buf * GBUFH + row * GST + off) * 2;
            uint32_t bd = sb + (uint32_t)(buf * GBUFH + 128 * GST + row * GST + off) * 2;
            cp_async16(ad, Ag0 + k0);       cp_async16(ad + 16, Ag0 + k0 + 8);
            cp_async16(bd, Bg0 + k0);       cp_async16(bd + 16, Bg0 + k0 + 8);
        }
        cp_commit();
        cp_wait1();
        __syncthreads();

        const __half* Ab = smh + (s & 1) * GBUFH;
        const __half* Bb = Ab + 128 * GST;
        #pragma unroll
        for (int ks = 0; ks < 2; ks++) {
            uint32_t af[2][4];
            #pragma unroll
            for (int im = 0; im < 2; im++) {
                const int m0 = wm * 32 + im * 16;
                af[im][0] = *(const uint32_t*)&Ab[(m0 + r) * GST + ks * 16 + 2 * c];
                af[im][1] = *(const uint32_t*)&Ab[(m0 + r + 8) * GST + ks * 16 + 2 * c];
                af[im][2] = *(const uint32_t*)&Ab[(m0 + r) * GST + ks * 16 + 2 * c + 8];
                af[im][3] = *(const uint32_t*)&Ab[(m0 + r + 8) * GST + ks * 16 + 2 * c + 8];
            }
            #pragma unroll
            for (int nt = 0; nt < 8; nt++) {
                const int n0 = wn * 64 + nt * 8;
                uint32_t bf[2];
                bf[0] = *(const uint32_t*)&Bb[(n0 + r) * GST + ks * 16 + 2 * c];
                bf[1] = *(const uint32_t*)&Bb[(n0 + r) * GST + ks * 16 + 2 * c + 8];
                mma_f16(acc[0][nt], af[0], bf);
                mma_f16(acc[1][nt], af[1], bf);
            }
        }
        __syncthreads();
    }

    #pragma unroll
    for (int im = 0; im < 2; im++) {
        #pragma unroll
        for (int nt = 0; nt < 8; nt++) {
            const int m = bm + wm * 32 + im * 16 + r;
            const int n = bn + wn * 64 + nt * 8 + 2 * c;
            float2 bz = *(const float2*)&bias[n];
            float v00 = acc[im][nt][0] + bz.x, v01 = acc[im][nt][1] + bz.y;
            float v10 = acc[im][nt][2] + bz.x, v11 = acc[im][nt][3] + bz.y;
            if (mode == 0) {
                const int bb = m >> 10, ss = m & 1023;
                const int hh = n >> 6, dd = n & 63;
                __half* dst = ((mat == 0) ? g_Qh : (mat == 1) ? g_Kh : g_Vh)
                            + ((size_t)((bb * NH + hh) * SEQ + ss)) * DK + dd;
                *(uint32_t*)dst = pack_h2(v00, v01);
                *(uint32_t*)(dst + 8 * DK) = pack_h2(v10, v11);
            } else {
                float* dst = Cout + (size_t)m * 1024 + n;
                float2 a0 = { v00, v01 }, a1 = { v10, v11 };
                *(float2*)dst = a0;
                *(float2*)(dst + 8 * 1024) = a1;
            }
        }
    }
}

// ---------------------------------------------------------------------------
// Geometry bias v2 (fp16, mask folded): thread handles a k-PAIR for all 16
// heads -> 4B coalesced half2 stores.
// ---------------------------------------------------------------------------
__global__ __launch_bounds__(256)
void geom_bias_kernel(const float* __restrict__ geom, const float* __restrict__ Wg,
                      const float* __restrict__ bg, const int* __restrict__ mask)
{
    __shared__ float wgs[7][16];
    __shared__ float bgs[16];
    int tid = threadIdx.x;
    if (tid < 112) wgs[tid / 16][tid % 16] = Wg[tid];
    if (tid < 16)  bgs[tid] = bg[tid];
    __syncthreads();

    size_t idx = (size_t)blockIdx.x * 256 + tid;   // over b*q*k2 (2^21)
    const int k2 = (int)(idx & 511);
    const int q  = (int)((idx >> 9) & 1023);
    const int b  = (int)(idx >> 19);
    const int k  = 2 * k2;

    const float2* gp = (const float2*)(geom + ((size_t)(b * 1024 + q) * 1024 + k) * 7);
    float2 t[7];
    #pragma unroll
    for (int i = 0; i < 7; i++) t[i] = gp[i];
    // elements 0..13: ga[j]=elem j (k), gb[j]=elem 7+j (k+1)
    float ga[7], gb[7];
    ga[0]=t[0].x; ga[1]=t[0].y; ga[2]=t[1].x; ga[3]=t[1].y; ga[4]=t[2].x; ga[5]=t[2].y; ga[6]=t[3].x;
    gb[0]=t[3].y; gb[1]=t[4].x; gb[2]=t[4].y; gb[3]=t[5].x; gb[4]=t[5].y; gb[5]=t[6].x; gb[6]=t[6].y;

    const bool live0 = mask[b * SEQ + k] != 0;
    const bool live1 = mask[b * SEQ + k + 1] != 0;
    __half2* outp = (__half2*)(g_biash + ((size_t)(b * NH) * SEQ + q) * SEQ + k);

    #pragma unroll
    for (int h = 0; h < NH; h++) {
        float va = bgs[h], vb = bgs[h];
        #pragma unroll
        for (int i = 0; i < 7; i++) {
            va += ga[i] * wgs[i][h];
            vb += gb[i] * wgs[i][h];
        }
        __half2 o = __floats2half2_rn(live0 ? va : -30000.f, live1 ? vb : -30000.f);
        outp[(size_t)h * (SEQ * SEQ / 2)] = o;
    }
}

// ---------------------------------------------------------------------------
// fp16 flash attention: 256 thr / 8 warps, q-tile 128, m16n8k16.
// Q frags in regs; K ldmatrix.x4; V ldmatrix.x4.trans; P register-only.
// K/V/bias cp.async double-buffered.
// ---------------------------------------------------------------------------
#define AVS 72
#define KT (64 * AVS)                              // K or V tile (halfs)
#define BT (128 * AVS)                             // bias tile (halfs)
#define AOFF_K(buf) ((buf) * KT)
#define AOFF_V(buf) (2 * KT + (buf) * KT)
#define AOFF_B(buf) (4 * KT + (buf) * BT)
#define ASMEM_BYTES ((4 * KT + 2 * BT) * 2)        // 73728 B

__global__ __launch_bounds__(256, 2)
void attn_h()
{
    extern __shared__ __half smh[];
    const uint32_t sb = smem_u32(smh);

    const int qb = blockIdx.x * 128;
    const int h  = blockIdx.y;
    const int b  = blockIdx.z;
    const __half* Qp = g_Qh + (size_t)((b * NH + h) * SEQ) * DK;
    const __half* Kp = g_Kh + (size_t)((b * NH + h) * SEQ) * DK;
    const __half* Vp = g_Vh + (size_t)((b * NH + h) * SEQ) * DK;
    const __half* Bp = g_biash + (size_t)(b * NH + h) * SEQ * SEQ;

    const int tid = threadIdx.x;
    const int lane = tid & 31, wid = tid >> 5;
    const int r = lane >> 2, c = lane & 3;
    const int q0 = wid * 16;

    const int rkv  = tid >> 2;             // 0..63
    const int okv  = (tid & 3) * 16;       // K/V segment
    const int rbx  = tid >> 1;             // 0..127
    const int obx  = (tid & 1) * 32;       // bias segment

    // Q fragments resident in registers
    uint32_t qf[4][4];
    {
        const __half* qr0 = Qp + (size_t)(qb + q0 + r) * DK;
        const __half* qr1 = Qp + (size_t)(qb + q0 + r + 8) * DK;
        #pragma unroll
        for (int ks = 0; ks < 4; ks++) {
            qf[ks][0] = *(const uint32_t*)&qr0[ks * 16 + 2 * c];
            qf[ks][1] = *(const uint32_t*)&qr1[ks * 16 + 2 * c];
            qf[ks][2] = *(const uint32_t*)&qr0[ks * 16 + 2 * c + 8];
            qf[ks][3] = *(const uint32_t*)&qr1[ks * 16 + 2 * c + 8];
        }
    }

    // prologue: tile 0
    {
        const __half* Kg = Kp + (size_t)rkv * DK + okv;
        const __half* Vg = Vp + (size_t)rkv * DK + okv;
        const __half* Bg = Bp + (size_t)(qb + rbx) * SEQ + obx;
        uint32_t kd = sb + (uint32_t)(AOFF_K(0) + rkv * AVS + okv) * 2;
        uint32_t vd = sb + (uint32_t)(AOFF_V(0) + rkv * AVS + okv) * 2;
        uint32_t bd = sb + (uint32_t)(AOFF_B(0) + rbx * AVS + obx) * 2;
        cp_async16(kd, Kg);       cp_async16(kd + 16, Kg + 8);
        cp_async16(vd, Vg);       cp_async16(vd + 16, Vg + 8);
        #pragma unroll
        for (int j = 0; j < 4; j++) cp_async16(bd + j * 16, Bg + j * 8);
        cp_commit();
    }

    float oAcc[8][4];
    #pragma unroll
    for (int dt = 0; dt < 8; dt++)
        #pragma unroll
        for (int j = 0; j < 4; j++) oAcc[dt][j] = 0.f;
    float mA = -1e30f, mB = -1e30f, lA = 0.f, lB = 0.f;

    for (int kt = 0; kt < 16; kt++) {
        if (kt < 15) {
            const int buf = (kt + 1) & 1;
            const int kb2 = (kt + 1) * 64;
            const __half* Kg = Kp + (size_t)(kb2 + rkv) * DK + okv;
            const __half* Vg = Vp + (size_t)(kb2 + rkv) * DK + okv;
            const __half* Bg = Bp + (size_t)(qb + rbx) * SEQ + kb2 + obx;
            uint32_t kd = sb + (uint32_t)(AOFF_K(buf) + rkv * AVS + okv) * 2;
            uint32_t vd = sb + (uint32_t)(AOFF_V(buf) + rkv * AVS + okv) * 2;
            uint32_t bd = sb + (uint32_t)(AOFF_B(buf) + rbx * AVS + obx) * 2;
            cp_async16(kd, Kg);       cp_async16(kd + 16, Kg + 8);
            cp_async16(vd, Vg);       cp_async16(vd + 16, Vg + 8);
            #pragma unroll
            for (int j = 0; j < 4; j++) cp_async16(bd + j * 16, Bg + j * 8);
        }
        cp_commit();
        cp_wait1();
        __syncthreads();

        const int buf = kt & 1;
        const uint32_t kbase = sb + (uint32_t)AOFF_K(buf) * 2;
        const uint32_t vbase = sb + (uint32_t)AOFF_V(buf) * 2;
        const __half* Bsm = smh + AOFF_B(buf);

        // ---- S = Q K^T ----
        float sAcc[8][4];
        #pragma unroll
        for (int nt = 0; nt < 8; nt++)
            #pragma unroll
            for (int j = 0; j < 4; j++) sAcc[nt][j] = 0.f;

        const int kmat = lane >> 3;
        const int krow_in = lane & 7;
        #pragma unroll
        for (int ks = 0; ks < 4; ks++) {
            #pragma unroll
            for (int ntp = 0; ntp < 4; ntp++) {
                const int seqrow = ntp * 16 + ((kmat >> 1) & 1) * 8 + krow_in;
                const int col = ks * 16 + (kmat & 1) * 8;
                uint32_t addr = kbase + (uint32_t)(seqrow * AVS + col) * 2;
                uint32_t d0, d1, d2, d3;
                ldsm_x4(d0, d1, d2, d3, addr);
                uint32_t b01[2] = { d0, d1 };
                uint32_t b23[2] = { d2, d3 };
                mma_f16(sAcc[2 * ntp],     qf[ks], b01);
                mma_f16(sAcc[2 * ntp + 1], qf[ks], b23);
            }
        }

        // ---- scale + bias (smem, mask pre-folded), row max ----
        float mxA = -1e30f, mxB = -1e30f;
        #pragma unroll
        for (int nt = 0; nt < 8; nt++) {
            uint32_t uA = *(const uint32_t*)&Bsm[(q0 + r) * AVS + nt * 8 + 2 * c];
            uint32_t uB = *(const uint32_t*)&Bsm[(q0 + r + 8) * AVS + nt * 8 + 2 * c];
            float2 bzA = __half22float2(*(__half2*)&uA);
            float2 bzB = __half22float2(*(__half2*)&uB);
            sAcc[nt][0] = fmaf(sAcc[nt][0], 0.125f, bzA.x);
            sAcc[nt][1] = fmaf(sAcc[nt][1], 0.125f, bzA.y);
            sAcc[nt][2] = fmaf(sAcc[nt][2], 0.125f, bzB.x);
            sAcc[nt][3] = fmaf(sAcc[nt][3], 0.125f, bzB.y);
            mxA = fmaxf(mxA, fmaxf(sAcc[nt][0], sAcc[nt][1]));
            mxB = fmaxf(mxB, fmaxf(sAcc[nt][2], sAcc[nt][3]));
        }
        mxA = fmaxf(mxA, __shfl_xor_sync(0xffffffffu, mxA, 1));
        mxA = fmaxf(mxA, __shfl_xor_sync(0xffffffffu, mxA, 2));
        mxB = fmaxf(mxB, __shfl_xor_sync(0xffffffffu, mxB, 1));
        mxB = fmaxf(mxB, __shfl_xor_sync(0xffffffffu, mxB, 2));

        const float mnA = fmaxf(mA, mxA);
        const float mnB = fmaxf(mB, mxB);
        float sumA = 0.f, sumB = 0.f;
        #pragma unroll
        for (int nt = 0; nt < 8; nt++) {
            sAcc[nt][0] = __expf(sAcc[nt][0] - mnA);
            sAcc[nt][1] = __expf(sAcc[nt][1] - mnA);
            sAcc[nt][2] = __expf(sAcc[nt][2] - mnB);
            sAcc[nt][3] = __expf(sAcc[nt][3] - mnB);
            sumA += sAcc[nt][0] + sAcc[nt][1];
            sumB += sAcc[nt][2] + sAcc[nt][3];
        }
        sumA += __shfl_xor_sync(0xffffffffu, sumA, 1);
        sumA += __shfl_xor_sync(0xffffffffu, sumA, 2);
        sumB += __shfl_xor_sync(0xffffffffu, sumB, 1);
        sumB += __shfl_xor_sync(0xffffffffu, sumB, 2);

        const float sclA = __expf(mA - mnA);
        const float sclB = __expf(mB - mnB);
        lA = lA * sclA + sumA;  mA = mnA;
        lB = lB * sclB + sumB;  mB = mnB;
        #pragma unroll
        for (int dt = 0; dt < 8; dt++) {
            oAcc[dt][0] *= sclA;  oAcc[dt][1] *= sclA;
            oAcc[dt][2] *= sclB;  oAcc[dt][3] *= sclB;
        }

        // ---- O += P V ----
        #pragma unroll
        for (int ks = 0; ks < 4; ks++) {
            uint32_t pa[4];
            pa[0] = pack_h2(sAcc[2 * ks][0],     sAcc[2 * ks][1]);
            pa[1] = pack_h2(sAcc[2 * ks][2],     sAcc[2 * ks][3]);
            pa[2] = pack_h2(sAcc[2 * ks + 1][0], sAcc[2 * ks + 1][1]);
            pa[3] = pack_h2(sAcc[2 * ks + 1][2], sAcc[2 * ks + 1][3]);
            #pragma unroll
            for (int dtp = 0; dtp < 4; dtp++) {
                const int vrow = ks * 16 + (kmat & 1) * 8 + krow_in;
                const int vcol = dtp * 16 + ((kmat >> 1) & 1) * 8;
                uint32_t addr = vbase + (uint32_t)(vrow * AVS + vcol) * 2;
                uint32_t d0, d1, d2, d3;
                ldsm_x4_t(d0, d1, d2, d3, addr);
                uint32_t b01[2] = { d0, d1 };
                uint32_t b23[2] = { d2, d3 };
                mma_f16(oAcc[2 * dtp],     pa, b01);
                mma_f16(oAcc[2 * dtp + 1], pa, b23);
            }
        }
        __syncthreads();
    }

    // ---- normalize + write ctx (fp16) ----
    const float iA = 1.f / lA;
    const float iB = 1.f / lB;
    __half* Op0 = g_ctxh + (size_t)(b * SEQ + qb + q0 + r) * DMODEL + h * 64 + 2 * c;
    __half* Op1 = Op0 + (size_t)8 * DMODEL;
    #pragma unroll
    for (int dt = 0; dt < 8; dt++) {
        *(uint32_t*)(Op0 + dt * 8) = pack_h2(oAcc[dt][0] * iA, oAcc[dt][1] * iA);
        *(uint32_t*)(Op1 + dt * 8) = pack_h2(oAcc[dt][2] * iB, oAcc[dt][3] * iB);
    }
}

// ---------------------------------------------------------------------------
extern "C" void kernel_launch(void* const* d_in, const int* in_sizes, int n_in,
                              void* d_out, int out_size)
{
    const float* x    = (const float*)d_in[0];
    const float* geom = (const float*)d_in[1];
    const int*   mask = (const int*)d_in[2];
    const float* Wq = (const float*)d_in[3];
    const float* bq = (const float*)d_in[4];
    const float* Wk = (const float*)d_in[5];
    const float* bk = (const float*)d_in[6];
    const float* Wv = (const float*)d_in[7];
    const float* bv = (const float*)d_in[8];
    const float* Wo = (const float*)d_in[9];
    const float* bo = (const float*)d_in[10];
    const float* Wg = (const float*)d_in[11];
    const float* bg = (const float*)d_in[12];
    float* out = (float*)d_out;

    cudaFuncSetAttribute(gemm_h, cudaFuncAttributeMaxDynamicSharedMemorySize, GSMEM_BYTES);
    cudaFuncSetAttribute(attn_h, cudaFuncAttributeMaxDynamicSharedMemorySize, ASMEM_BYTES);

    convert_x<<<(BATCH * SEQ * DMODEL) / (256 * 4), 256>>>(x);
    transpose_w_h<<<dim3(32, 32, 4), dim3(32, 8)>>>(Wq, Wk, Wv, Wo);

    gemm_h<<<dim3(24, 32), 256, GSMEM_BYTES>>>(bq, bk, bv, nullptr, 0);

    geom_bias_kernel<<<(BATCH * SEQ * SEQ / 2) / 256, 256>>>(geom, Wg, bg, mask);

    attn_h<<<dim3(SEQ / 128, NH, BATCH), 256, ASMEM_BYTES>>>();

    gemm_h<<<dim3(8, 32), 256, GSMEM_BYTES>>>(bo, nullptr, nullptr, out, 1);
}

// round 9
// speedup vs baseline: 2.2307x; 1.0391x over previous
#include <cuda_runtime.h>
#include <cuda_fp16.h>
#include <math.h>
#include <cstdint>

#define BATCH  4
#define SEQ    1024
#define DMODEL 1024
#define NH     16
#define DK     64
#define LOG2E  1.4426950408889634f

// ---------------- scratch (device globals: allocation-free) ----------------
__device__ __half g_xh[BATCH * SEQ * DMODEL];
__device__ __half g_WTh[4 * 1024 * 1024];     // W^T per matrix: [n][k] fp16
__device__ __half g_Qh[BATCH * NH * SEQ * DK];
__device__ __half g_Kh[BATCH * NH * SEQ * DK];
__device__ __half g_Vh[BATCH * NH * SEQ * DK];
__device__ __half g_ctxh[BATCH * SEQ * DMODEL];
__device__ __half g_biash[(size_t)BATCH * NH * SEQ * SEQ];  // bias*log2e, mask folded

// ---------------- helpers ----------------
__device__ __forceinline__ void mma_f16(float c[4], const uint32_t a[4], const uint32_t b[2]) {
    asm volatile("mma.sync.aligned.m16n8k16.row.col.f32.f16.f16.f32 "
                 "{%0,%1,%2,%3}, {%4,%5,%6,%7}, {%8,%9}, {%0,%1,%2,%3};"
                 : "+f"(c[0]), "+f"(c[1]), "+f"(c[2]), "+f"(c[3])
                 : "r"(a[0]), "r"(a[1]), "r"(a[2]), "r"(a[3]), "r"(b[0]), "r"(b[1]));
}
__device__ __forceinline__ uint32_t smem_u32(const void* p) {
    uint32_t a;
    asm("{ .reg .u64 t; cvta.to.shared.u64 t, %1; cvt.u32.u64 %0, t; }" : "=r"(a) : "l"(p));
    return a;
}
__device__ __forceinline__ void cp_async16(uint32_t s, const void* g) {
    asm volatile("cp.async.cg.shared.global [%0], [%1], 16;" :: "r"(s), "l"(g) : "memory");
}
__device__ __forceinline__ void cp_commit() {
    asm volatile("cp.async.commit_group;" ::: "memory");
}
__device__ __forceinline__ void cp_wait1() {
    asm volatile("cp.async.wait_group 1;" ::: "memory");
}
__device__ __forceinline__ void ldsm_x4(uint32_t& d0, uint32_t& d1, uint32_t& d2, uint32_t& d3,
                                        uint32_t addr) {
    asm volatile("ldmatrix.sync.aligned.m8n8.x4.shared.b16 {%0,%1,%2,%3}, [%4];"
                 : "=r"(d0), "=r"(d1), "=r"(d2), "=r"(d3) : "r"(addr));
}
__device__ __forceinline__ void ldsm_x4_t(uint32_t& d0, uint32_t& d1, uint32_t& d2, uint32_t& d3,
                                          uint32_t addr) {
    asm volatile("ldmatrix.sync.aligned.m8n8.x4.trans.shared.b16 {%0,%1,%2,%3}, [%4];"
                 : "=r"(d0), "=r"(d1), "=r"(d2), "=r"(d3) : "r"(addr));
}
__device__ __forceinline__ uint32_t pack_h2(float lo, float hi) {
    __half2 h = __floats2half2_rn(lo, hi);
    return *(uint32_t*)&h;
}

// ---------------------------------------------------------------------------
// prep: z<4 -> weight transpose+convert; z==4 -> x fp32->fp16
// (single launch so attention lands on profiled slot #4)
// ---------------------------------------------------------------------------
__global__ void prep(const float* __restrict__ x,
                     const float* __restrict__ W0, const float* __restrict__ W1,
                     const float* __restrict__ W2, const float* __restrict__ W3)
{
    if (blockIdx.z < 4) {
        __shared__ float t[32][33];
        const float* W = (blockIdx.z == 0) ? W0 : (blockIdx.z == 1) ? W1
                       : (blockIdx.z == 2) ? W2 : W3;
        __half* Wt = g_WTh + (size_t)blockIdx.z * 1024 * 1024;
        int bx = blockIdx.x * 32, by = blockIdx.y * 32;
        int tx = threadIdx.x, ty = threadIdx.y;
        #pragma unroll
        for (int i = 0; i < 32; i += 8)
            t[ty + i][tx] = W[(size_t)(by + ty + i) * 1024 + bx + tx];
        __syncthreads();
        #pragma unroll
        for (int i = 0; i < 32; i += 8)
            Wt[(size_t)(bx + ty + i) * 1024 + by + tx] = __float2half(t[tx][ty + i]);
    } else {
        const int tid = threadIdx.y * 32 + threadIdx.x;
        size_t base = (((size_t)blockIdx.y * 32 + blockIdx.x) * 256 + tid) * 16;
        #pragma unroll
        for (int j = 0; j < 4; j++) {
            float4 v = *(const float4*)(x + base + j * 4);
            *(uint32_t*)&g_xh[base + j * 4]     = pack_h2(v.x, v.y);
            *(uint32_t*)&g_xh[base + j * 4 + 2] = pack_h2(v.z, v.w);
        }
    }
}

// ---------------------------------------------------------------------------
// fp16 GEMM (m16n8k16) with ldmatrix fragment loads.
// CTA 128x128, k-slab 32, cp.async double-buffered.
// mode 0: QKV fused -> g_{Q,K,V}h [b,h,s,dk]; mode 1: outproj -> fp32 Cout.
// ---------------------------------------------------------------------------
#define GST 40
#define GBUFH (2 * 128 * GST)
#define GSMEM_BYTES (2 * GBUFH * 2)

__global__ __launch_bounds__(256)
void gemm_h(const float* __restrict__ bias0, const float* __restrict__ bias1,
            const float* __restrict__ bias2, float* __restrict__ Cout, int mode)
{
    extern __shared__ __half smh[];
    const uint32_t sb = smem_u32(smh);
    const int tid = threadIdx.x, lane = tid & 31;
    const int wid = tid >> 5;
    const int wm = wid & 3, wn = wid >> 2;
    const int r = lane >> 2, c = lane & 3;
    const int kmat = lane >> 3, krow = lane & 7;

    int mat, bn;
    const float* bias;
    if (mode == 0) {
        mat = blockIdx.x >> 3;
        bn = (blockIdx.x & 7) * 128;
        bias = (mat == 0) ? bias0 : (mat == 1) ? bias1 : bias2;
    } else {
        mat = 3;
        bn = blockIdx.x * 128;
        bias = bias0;
    }
    const int bm = blockIdx.y * 128;
    const __half* Ah = (mode == 0) ? g_xh : g_ctxh;
    const __half* Bh = g_WTh + (size_t)mat * 1024 * 1024;

    const int row = tid >> 1;
    const int off = (tid & 1) * 16;

    const __half* Ag0 = Ah + (size_t)(bm + row) * 1024 + off;
    const __half* Bg0 = Bh + (size_t)(bn + row) * 1024 + off;

    {
        uint32_t ad = sb + (uint32_t)(row * GST + off) * 2;
        uint32_t bd = sb + (uint32_t)(128 * GST + row * GST + off) * 2;
        cp_async16(ad, Ag0);       cp_async16(ad + 16, Ag0 + 8);
        cp_async16(bd, Bg0);       cp_async16(bd + 16, Bg0 + 8);
        cp_commit();
    }

    float acc[2][8][4];
    #pragma unroll
    for (int im = 0; im < 2; im++)
        #pragma unroll
        for (int nt = 0; nt < 8; nt++)
            #pragma unroll
            for (int j = 0; j < 4; j++) acc[im][nt][j] = 0.f;

    for (int s = 0; s < 32; s++) {
        if (s < 31) {
            const int buf = (s + 1) & 1;
            const int k0 = (s + 1) * 32;
            uint32_t ad = sb + (uint32_t)(buf * GBUFH + row * GST + off) * 2;
            uint32_t bd = sb + (uint32_t)(buf * GBUFH + 128 * GST + row * GST + off) * 2;
            cp_async16(ad, Ag0 + k0);       cp_async16(ad + 16, Ag0 + k0 + 8);
            cp_async16(bd, Bg0 + k0);       cp_async16(bd + 16, Bg0 + k0 + 8);
        }
        cp_commit();
        cp_wait1();
        __syncthreads();

        const uint32_t abase = sb + (uint32_t)((s & 1) * GBUFH) * 2;
        const uint32_t bbase = abase + (uint32_t)(128 * GST) * 2;
        #pragma unroll
        for (int ks = 0; ks < 2; ks++) {
            // A fragments: row = m0 + (kmat&1)*8 + krow, col = ks*16 + (kmat>>1)*8
            uint32_t af[2][4];
            #pragma unroll
            for (int im = 0; im < 2; im++) {
                const int arow = wm * 32 + im * 16 + (kmat & 1) * 8 + krow;
                const int acol = ks * 16 + (kmat >> 1) * 8;
                ldsm_x4(af[im][0], af[im][1], af[im][2], af[im][3],
                        abase + (uint32_t)(arow * GST + acol) * 2);
            }
            // B fragments: 4 ldsm.x4 cover nt pairs
            uint32_t bf[8][2];
            #pragma unroll
            for (int ntp = 0; ntp < 4; ntp++) {
                const int brow = wn * 64 + ntp * 16 + ((kmat >> 1) & 1) * 8 + krow;
                const int bcol = ks * 16 + (kmat & 1) * 8;
                uint32_t d0, d1, d2, d3;
                ldsm_x4(d0, d1, d2, d3, bbase + (uint32_t)(brow * GST + bcol) * 2);
                bf[2 * ntp][0] = d0;  bf[2 * ntp][1] = d1;
                bf[2 * ntp + 1][0] = d2;  bf[2 * ntp + 1][1] = d3;
            }
            #pragma unroll
            for (int nt = 0; nt < 8; nt++) {
                mma_f16(acc[0][nt], af[0], bf[nt]);
                mma_f16(acc[1][nt], af[1], bf[nt]);
            }
        }
        __syncthreads();
    }

    #pragma unroll
    for (int im = 0; im < 2; im++) {
        #pragma unroll
        for (int nt = 0; nt < 8; nt++) {
            const int m = bm + wm * 32 + im * 16 + r;
            const int n = bn + wn * 64 + nt * 8 + 2 * c;
            float2 bz = *(const float2*)&bias[n];
            float v00 = acc[im][nt][0] + bz.x, v01 = acc[im][nt][1] + bz.y;
            float v10 = acc[im][nt][2] + bz.x, v11 = acc[im][nt][3] + bz.y;
            if (mode == 0) {
                const int bb = m >> 10, ss = m & 1023;
                const int hh = n >> 6, dd = n & 63;
                __half* dst = ((mat == 0) ? g_Qh : (mat == 1) ? g_Kh : g_Vh)
                            + ((size_t)((bb * NH + hh) * SEQ + ss)) * DK + dd;
                *(uint32_t*)dst = pack_h2(v00, v01);
                *(uint32_t*)(dst + 8 * DK) = pack_h2(v10, v11);
            } else {
                float* dst = Cout + (size_t)m * 1024 + n;
                float2 a0 = { v00, v01 }, a1 = { v10, v11 };
                *(float2*)dst = a0;
                *(float2*)(dst + 8 * 1024) = a1;
            }
        }
    }
}

// ---------------------------------------------------------------------------
// Geometry bias (fp16, mask folded, pre-scaled by log2e for exp2 softmax)
// ---------------------------------------------------------------------------
__global__ __launch_bounds__(256)
void geom_bias_kernel(const float* __restrict__ geom, const float* __restrict__ Wg,
                      const float* __restrict__ bg, const int* __restrict__ mask)
{
    __shared__ float wgs[7][16];
    __shared__ float bgs[16];
    int tid = threadIdx.x;
    if (tid < 112) wgs[tid / 16][tid % 16] = Wg[tid] * LOG2E;
    if (tid < 16)  bgs[tid] = bg[tid] * LOG2E;
    __syncthreads();

    size_t idx = (size_t)blockIdx.x * 256 + tid;   // over b*q*k2 (2^21)
    const int k2 = (int)(idx & 511);
    const int q  = (int)((idx >> 9) & 1023);
    const int b  = (int)(idx >> 19);
    const int k  = 2 * k2;

    const float2* gp = (const float2*)(geom + ((size_t)(b * 1024 + q) * 1024 + k) * 7);
    float2 t[7];
    #pragma unroll
    for (int i = 0; i < 7; i++) t[i] = gp[i];
    float ga[7], gb[7];
    ga[0]=t[0].x; ga[1]=t[0].y; ga[2]=t[1].x; ga[3]=t[1].y; ga[4]=t[2].x; ga[5]=t[2].y; ga[6]=t[3].x;
    gb[0]=t[3].y; gb[1]=t[4].x; gb[2]=t[4].y; gb[3]=t[5].x; gb[4]=t[5].y; gb[5]=t[6].x; gb[6]=t[6].y;

    const bool live0 = mask[b * SEQ + k] != 0;
    const bool live1 = mask[b * SEQ + k + 1] != 0;
    __half2* outp = (__half2*)(g_biash + ((size_t)(b * NH) * SEQ + q) * SEQ + k);

    #pragma unroll
    for (int h = 0; h < NH; h++) {
        float va = bgs[h], vb = bgs[h];
        #pragma unroll
        for (int i = 0; i < 7; i++) {
            va += ga[i] * wgs[i][h];
            vb += gb[i] * wgs[i][h];
        }
        __half2 o = __floats2half2_rn(live0 ? va : -43000.f, live1 ? vb : -43000.f);
        outp[(size_t)h * (SEQ * SEQ / 2)] = o;
    }
}

// ---------------------------------------------------------------------------
// fp16 flash attention: 256 thr / 8 warps, q-tile 128, m16n8k16, exp2 softmax.
// ---------------------------------------------------------------------------
#define AVS 72
#define KTH (64 * AVS)
#define BTH (128 * AVS)
#define AOFF_K(buf) ((buf) * KTH)
#define AOFF_V(buf) (2 * KTH + (buf) * KTH)
#define AOFF_B(buf) (4 * KTH + (buf) * BTH)
#define ASMEM_BYTES ((4 * KTH + 2 * BTH) * 2)      // 73728 B

__global__ __launch_bounds__(256, 2)
void attn_h()
{
    extern __shared__ __half smh[];
    const uint32_t sb = smem_u32(smh);

    const int qb = blockIdx.x * 128;
    const int h  = blockIdx.y;
    const int b  = blockIdx.z;
    const __half* Qp = g_Qh + (size_t)((b * NH + h) * SEQ) * DK;
    const __half* Kp = g_Kh + (size_t)((b * NH + h) * SEQ) * DK;
    const __half* Vp = g_Vh + (size_t)((b * NH + h) * SEQ) * DK;
    const __half* Bp = g_biash + (size_t)(b * NH + h) * SEQ * SEQ;

    const int tid = threadIdx.x;
    const int lane = tid & 31, wid = tid >> 5;
    const int r = lane >> 2, c = lane & 3;
    const int q0 = wid * 16;

    const int rkv  = tid >> 2;
    const int okv  = (tid & 3) * 16;
    const int rbx  = tid >> 1;
    const int obx  = (tid & 1) * 32;

    uint32_t qf[4][4];
    {
        const __half* qr0 = Qp + (size_t)(qb + q0 + r) * DK;
        const __half* qr1 = Qp + (size_t)(qb + q0 + r + 8) * DK;
        #pragma unroll
        for (int ks = 0; ks < 4; ks++) {
            qf[ks][0] = *(const uint32_t*)&qr0[ks * 16 + 2 * c];
            qf[ks][1] = *(const uint32_t*)&qr1[ks * 16 + 2 * c];
            qf[ks][2] = *(const uint32_t*)&qr0[ks * 16 + 2 * c + 8];
            qf[ks][3] = *(const uint32_t*)&qr1[ks * 16 + 2 * c + 8];
        }
    }

    {
        const __half* Kg = Kp + (size_t)rkv * DK + okv;
        const __half* Vg = Vp + (size_t)rkv * DK + okv;
        const __half* Bg = Bp + (size_t)(qb + rbx) * SEQ + obx;
        uint32_t kd = sb + (uint32_t)(AOFF_K(0) + rkv * AVS + okv) * 2;
        uint32_t vd = sb + (uint32_t)(AOFF_V(0) + rkv * AVS + okv) * 2;
        uint32_t bd = sb + (uint32_t)(AOFF_B(0) + rbx * AVS + obx) * 2;
        cp_async16(kd, Kg);       cp_async16(kd + 16, Kg + 8);
        cp_async16(vd, Vg);       cp_async16(vd + 16, Vg + 8);
        #pragma unroll
        for (int j = 0; j < 4; j++) cp_async16(bd + j * 16, Bg + j * 8);
        cp_commit();
    }

    float oAcc[8][4];
    #pragma unroll
    for (int dt = 0; dt < 8; dt++)
        #pragma unroll
        for (int j = 0; j < 4; j++) oAcc[dt][j] = 0.f;
    float mA = -1e30f, mB = -1e30f, lA = 0.f, lB = 0.f;

    for (int kt = 0; kt < 16; kt++) {
        if (kt < 15) {
            const int buf = (kt + 1) & 1;
            const int kb2 = (kt + 1) * 64;
            const __half* Kg = Kp + (size_t)(kb2 + rkv) * DK + okv;
            const __half* Vg = Vp + (size_t)(kb2 + rkv) * DK + okv;
            const __half* Bg = Bp + (size_t)(qb + rbx) * SEQ + kb2 + obx;
            uint32_t kd = sb + (uint32_t)(AOFF_K(buf) + rkv * AVS + okv) * 2;
            uint32_t vd = sb + (uint32_t)(AOFF_V(buf) + rkv * AVS + okv) * 2;
            uint32_t bd = sb + (uint32_t)(AOFF_B(buf) + rbx * AVS + obx) * 2;
            cp_async16(kd, Kg);       cp_async16(kd + 16, Kg + 8);
            cp_async16(vd, Vg);       cp_async16(vd + 16, Vg + 8);
            #pragma unroll
            for (int j = 0; j < 4; j++) cp_async16(bd + j * 16, Bg + j * 8);
        }
        cp_commit();
        cp_wait1();
        __syncthreads();

        const int buf = kt & 1;
        const uint32_t kbase = sb + (uint32_t)AOFF_K(buf) * 2;
        const uint32_t vbase = sb + (uint32_t)AOFF_V(buf) * 2;
        const __half* Bsm = smh + AOFF_B(buf);

        float sAcc[8][4];
        #pragma unroll
        for (int nt = 0; nt < 8; nt++)
            #pragma unroll
            for (int j = 0; j < 4; j++) sAcc[nt][j] = 0.f;

        const int kmat = lane >> 3;
        const int krow_in = lane & 7;
        #pragma unroll
        for (int ks = 0; ks < 4; ks++) {
            #pragma unroll
            for (int ntp = 0; ntp < 4; ntp++) {
                const int seqrow = ntp * 16 + ((kmat >> 1) & 1) * 8 + krow_in;
                const int col = ks * 16 + (kmat & 1) * 8;
                uint32_t addr = kbase + (uint32_t)(seqrow * AVS + col) * 2;
                uint32_t d0, d1, d2, d3;
                ldsm_x4(d0, d1, d2, d3, addr);
                uint32_t b01[2] = { d0, d1 };
                uint32_t b23[2] = { d2, d3 };
                mma_f16(sAcc[2 * ntp],     qf[ks], b01);
                mma_f16(sAcc[2 * ntp + 1], qf[ks], b23);
            }
        }

        // scale (0.125*log2e) + bias (already *log2e), row max
        const float SC = 0.125f * LOG2E;
        float mxA = -1e30f, mxB = -1e30f;
        #pragma unroll
        for (int nt = 0; nt < 8; nt++) {
            uint32_t uA = *(const uint32_t*)&Bsm[(q0 + r) * AVS + nt * 8 + 2 * c];
            uint32_t uB = *(const uint32_t*)&Bsm[(q0 + r + 8) * AVS + nt * 8 + 2 * c];
            float2 bzA = __half22float2(*(__half2*)&uA);
            float2 bzB = __half22float2(*(__half2*)&uB);
            sAcc[nt][0] = fmaf(sAcc[nt][0], SC, bzA.x);
            sAcc[nt][1] = fmaf(sAcc[nt][1], SC, bzA.y);
            sAcc[nt][2] = fmaf(sAcc[nt][2], SC, bzB.x);
            sAcc[nt][3] = fmaf(sAcc[nt][3], SC, bzB.y);
            mxA = fmaxf(mxA, fmaxf(sAcc[nt][0], sAcc[nt][1]));
            mxB = fmaxf(mxB, fmaxf(sAcc[nt][2], sAcc[nt][3]));
        }
        mxA = fmaxf(mxA, __shfl_xor_sync(0xffffffffu, mxA, 1));
        mxA = fmaxf(mxA, __shfl_xor_sync(0xffffffffu, mxA, 2));
        mxB = fmaxf(mxB, __shfl_xor_sync(0xffffffffu, mxB, 1));
        mxB = fmaxf(mxB, __shfl_xor_sync(0xffffffffu, mxB, 2));

        const float mnA = fmaxf(mA, mxA);
        const float mnB = fmaxf(mB, mxB);
        float sumA = 0.f, sumB = 0.f;
        #pragma unroll
        for (int nt = 0; nt < 8; nt++) {
            sAcc[nt][0] = exp2f(sAcc[nt][0] - mnA);
            sAcc[nt][1] = exp2f(sAcc[nt][1] - mnA);
            sAcc[nt][2] = exp2f(sAcc[nt][2] - mnB);
            sAcc[nt][3] = exp2f(sAcc[nt][3] - mnB);
            sumA += sAcc[nt][0] + sAcc[nt][1];
            sumB += sAcc[nt][2] + sAcc[nt][3];
        }
        sumA += __shfl_xor_sync(0xffffffffu, sumA, 1);
        sumA += __shfl_xor_sync(0xffffffffu, sumA, 2);
        sumB += __shfl_xor_sync(0xffffffffu, sumB, 1);
        sumB += __shfl_xor_sync(0xffffffffu, sumB, 2);

        const float sclA = exp2f(mA - mnA);
        const float sclB = exp2f(mB - mnB);
        lA = lA * sclA + sumA;  mA = mnA;
        lB = lB * sclB + sumB;  mB = mnB;
        #pragma unroll
        for (int dt = 0; dt < 8; dt++) {
            oAcc[dt][0] *= sclA;  oAcc[dt][1] *= sclA;
            oAcc[dt][2] *= sclB;  oAcc[dt][3] *= sclB;
        }

        #pragma unroll
        for (int ks = 0; ks < 4; ks++) {
            uint32_t pa[4];
            pa[0] = pack_h2(sAcc[2 * ks][0],     sAcc[2 * ks][1]);
            pa[1] = pack_h2(sAcc[2 * ks][2],     sAcc[2 * ks][3]);
            pa[2] = pack_h2(sAcc[2 * ks + 1][0], sAcc[2 * ks + 1][1]);
            pa[3] = pack_h2(sAcc[2 * ks + 1][2], sAcc[2 * ks + 1][3]);
            #pragma unroll
            for (int dtp = 0; dtp < 4; dtp++) {
                const int vrow = ks * 16 + (kmat & 1) * 8 + krow_in;
                const int vcol = dtp * 16 + ((kmat >> 1) & 1) * 8;
                uint32_t addr = vbase + (uint32_t)(vrow * AVS + vcol) * 2;
                uint32_t d0, d1, d2, d3;
                ldsm_x4_t(d0, d1, d2, d3, addr);
                uint32_t b01[2] = { d0, d1 };
                uint32_t b23[2] = { d2, d3 };
                mma_f16(oAcc[2 * dtp],     pa, b01);
                mma_f16(oAcc[2 * dtp + 1], pa, b23);
            }
        }
        __syncthreads();
    }

    const float iA = 1.f / lA;
    const float iB = 1.f / lB;
    __half* Op0 = g_ctxh + (size_t)(b * SEQ + qb + q0 + r) * DMODEL + h * 64 + 2 * c;
    __half* Op1 = Op0 + (size_t)8 * DMODEL;
    #pragma unroll
    for (int dt = 0; dt < 8; dt++) {
        *(uint32_t*)(Op0 + dt * 8) = pack_h2(oAcc[dt][0] * iA, oAcc[dt][1] * iA);
        *(uint32_t*)(Op1 + dt * 8) = pack_h2(oAcc[dt][2] * iB, oAcc[dt][3] * iB);
    }
}

// ---------------------------------------------------------------------------
extern "C" void kernel_launch(void* const* d_in, const int* in_sizes, int n_in,
                              void* d_out, int out_size)
{
    const float* x    = (const float*)d_in[0];
    const float* geom = (const float*)d_in[1];
    const int*   mask = (const int*)d_in[2];
    const float* Wq = (const float*)d_in[3];
    const float* bq = (const float*)d_in[4];
    const float* Wk = (const float*)d_in[5];
    const float* bk = (const float*)d_in[6];
    const float* Wv = (const float*)d_in[7];
    const float* bv = (const float*)d_in[8];
    const float* Wo = (const float*)d_in[9];
    const float* bo = (const float*)d_in[10];
    const float* Wg = (const float*)d_in[11];
    const float* bg = (const float*)d_in[12];
    float* out = (float*)d_out;

    cudaFuncSetAttribute(gemm_h, cudaFuncAttributeMaxDynamicSharedMemorySize, GSMEM_BYTES);
    cudaFuncSetAttribute(attn_h, cudaFuncAttributeMaxDynamicSharedMemorySize, ASMEM_BYTES);

    // launch 1: prep (x convert + 4 weight transposes)
    prep<<<dim3(32, 32, 5), dim3(32, 8)>>>(x, Wq, Wk, Wv, Wo);

    // launch 2: QKV projections
    gemm_h<<<dim3(24, 32), 256, GSMEM_BYTES>>>(bq, bk, bv, nullptr, 0);

    // launch 3: geometric bias
    geom_bias_kernel<<<(BATCH * SEQ * SEQ / 2) / 256, 256>>>(geom, Wg, bg, mask);

    // launch 4: attention  (profiled slot)
    attn_h<<<dim3(SEQ / 128, NH, BATCH), 256, ASMEM_BYTES>>>();

    // launch 5: output projection
    gemm_h<<<dim3(8, 32), 256, GSMEM_BYTES>>>(bo, nullptr, nullptr, out, 1);
}